// round 4
// baseline (speedup 1.0000x reference)
#include <cuda_runtime.h>
#include <math.h>
#include <stdint.h>

#define BB 4
#define TT 1024
#define SS 576
#define HH 16
#define HD 64
#define DDEC 1024
#define DMLP 4096

// ---------------- scratch (device globals; no allocation allowed) ----------------
__device__ float g_h[4194304];        // LN output        [4096,1024]
__device__ float g_qkv[12582912];     // qkv [4096,3072] / reused as q  [4096,1024]
__device__ float g_tmp[4194304];      // sa / ca          [4096,1024]
__device__ float g_x1[4194304];
__device__ float g_x2[4194304];
__device__ float g_kc[2359296];       // cross K          [2304,1024]
__device__ float g_vc[2359296];       // cross V          [2304,1024]
__device__ float g_mlp[16777216];     // mlp hidden       [4096,4096]

// ---------------- LayerNorm: one block per row of 1024 ----------------
__global__ void ln_kernel(const float* __restrict__ x, const float* __restrict__ w,
                          const float* __restrict__ b, float* __restrict__ out) {
    __shared__ float red[256];
    int row = blockIdx.x, tid = threadIdx.x;
    const float4* xr = (const float4*)(x + (size_t)row * DDEC);
    float4 v = xr[tid];
    red[tid] = v.x + v.y + v.z + v.w;
    __syncthreads();
    #pragma unroll
    for (int o = 128; o > 0; o >>= 1) { if (tid < o) red[tid] += red[tid + o]; __syncthreads(); }
    float mean = red[0] * (1.0f / 1024.0f);
    __syncthreads();
    float dx = v.x - mean, dy = v.y - mean, dz = v.z - mean, dw = v.w - mean;
    red[tid] = dx * dx + dy * dy + dz * dz + dw * dw;
    __syncthreads();
    #pragma unroll
    for (int o = 128; o > 0; o >>= 1) { if (tid < o) red[tid] += red[tid + o]; __syncthreads(); }
    float rstd = rsqrtf(red[0] * (1.0f / 1024.0f) + 1e-5f);
    float4 wv = ((const float4*)w)[tid];
    float4 bv = ((const float4*)b)[tid];
    float4 o4;
    o4.x = dx * rstd * wv.x + bv.x;
    o4.y = dy * rstd * wv.y + bv.y;
    o4.z = dz * rstd * wv.z + bv.z;
    o4.w = dw * rstd * wv.w + bv.w;
    ((float4*)(out + (size_t)row * DDEC))[tid] = o4;
}

// ---------------- tf32 / async helpers ----------------
__device__ __forceinline__ float tf32r(float x) {
    uint32_t u;
    asm("cvt.rna.tf32.f32 %0, %1;" : "=r"(u) : "f"(x));
    return __uint_as_float(u);
}

__device__ __forceinline__ void mma_tf32(float (&d)[4], const float (&a)[4], const float (&b)[2]) {
    asm volatile(
        "mma.sync.aligned.m16n8k8.row.col.f32.tf32.tf32.f32 "
        "{%0,%1,%2,%3}, {%4,%5,%6,%7}, {%8,%9}, {%0,%1,%2,%3};"
        : "+f"(d[0]), "+f"(d[1]), "+f"(d[2]), "+f"(d[3])
        : "r"(__float_as_uint(a[0])), "r"(__float_as_uint(a[1])),
          "r"(__float_as_uint(a[2])), "r"(__float_as_uint(a[3])),
          "r"(__float_as_uint(b[0])), "r"(__float_as_uint(b[1])));
}

__device__ __forceinline__ void cp_async16(void* sdst, const void* gsrc) {
    uint32_t sa = (uint32_t)__cvta_generic_to_shared(sdst);
    asm volatile("cp.async.cg.shared.global [%0], [%1], 16;" :: "r"(sa), "l"(gsrc));
}
__device__ __forceinline__ void cp_commit() { asm volatile("cp.async.commit_group;"); }
template <int N>
__device__ __forceinline__ void cp_wait() { asm volatile("cp.async.wait_group %0;" :: "n"(N)); }

// ---------------- tf32 tensor GEMM: C = A@W + bias (+res) (GELU opt) ----------------
// block 128x128x32, 8 warps, 3-stage cp.async pipeline, tf32 cvt at fragment read
#define AS_LD 36
#define BS_LD 132
#define G_STAGE (128 * AS_LD + 32 * BS_LD)    // floats per stage = 8832
#define SMEM_GEMM (3 * G_STAGE)               // floats

template <bool GELU>
__global__ __launch_bounds__(256, 2) void gemm_tf32_kernel(
    const float* __restrict__ A, const float* __restrict__ W,
    const float* __restrict__ bias, const float* __restrict__ res,
    float* __restrict__ C, int M, int N, int K) {
    extern __shared__ float smem[];

    int tid = threadIdx.x;
    int warp = tid >> 5, lane = tid & 31;
    int warp_m = warp >> 2, warp_n = warp & 3;
    int g = lane >> 2, tg = lane & 3;
    int bm = blockIdx.y * 128, bn = blockIdx.x * 128;

    int a_row = tid >> 1, a_col = (tid & 1) * 16;   // 4x float4 per thread
    int b_row = tid >> 3, b_col = (tid & 7) * 16;   // 4x float4 per thread
    const float* Ag = A + (size_t)(bm + a_row) * K + a_col;
    const float* Wg = W + (size_t)b_row * N + bn + b_col;

    float acc[4][4][4];
    #pragma unroll
    for (int i = 0; i < 4; i++)
        #pragma unroll
        for (int j = 0; j < 4; j++)
            #pragma unroll
            for (int c = 0; c < 4; c++) acc[i][j][c] = 0.f;

    int kTiles = K >> 5;

    // prologue: issue stages 0,1
    #pragma unroll
    for (int s = 0; s < 2; s++) {
        float* As = smem + s * G_STAGE;
        float* Bs = As + 128 * AS_LD;
        const float* ap = Ag + s * 32;
        const float* bp = Wg + (size_t)(s * 32) * N;
        #pragma unroll
        for (int i = 0; i < 4; i++) cp_async16(&As[a_row * AS_LD + a_col + i * 4], ap + i * 4);
        #pragma unroll
        for (int i = 0; i < 4; i++) cp_async16(&Bs[b_row * BS_LD + b_col + i * 4], bp + i * 4);
        cp_commit();
    }

    for (int kt = 0; kt < kTiles; kt++) {
        cp_wait<1>();
        __syncthreads();
        int buf = kt % 3;
        float* Ab = smem + buf * G_STAGE;
        float* Bb = Ab + 128 * AS_LD;

        #pragma unroll
        for (int kk = 0; kk < 4; kk++) {
            int kb = kk << 3;
            float af[4][4], bf[4][2];
            #pragma unroll
            for (int mt = 0; mt < 4; mt++) {
                int m0 = warp_m * 64 + mt * 16 + g;
                af[mt][0] = tf32r(Ab[m0 * AS_LD + kb + tg]);
                af[mt][1] = tf32r(Ab[(m0 + 8) * AS_LD + kb + tg]);
                af[mt][2] = tf32r(Ab[m0 * AS_LD + kb + tg + 4]);
                af[mt][3] = tf32r(Ab[(m0 + 8) * AS_LD + kb + tg + 4]);
            }
            #pragma unroll
            for (int nt = 0; nt < 4; nt++) {
                int n0 = warp_n * 32 + nt * 8 + g;
                bf[nt][0] = tf32r(Bb[(kb + tg) * BS_LD + n0]);
                bf[nt][1] = tf32r(Bb[(kb + tg + 4) * BS_LD + n0]);
            }
            #pragma unroll
            for (int mt = 0; mt < 4; mt++)
                #pragma unroll
                for (int nt = 0; nt < 4; nt++) mma_tf32(acc[mt][nt], af[mt], bf[nt]);
        }

        int ktn = kt + 2;
        if (ktn < kTiles) {
            float* As = smem + (ktn % 3) * G_STAGE;
            float* Bs = As + 128 * AS_LD;
            const float* ap = Ag + ktn * 32;
            const float* bp = Wg + (size_t)(ktn * 32) * N;
            #pragma unroll
            for (int i = 0; i < 4; i++) cp_async16(&As[a_row * AS_LD + a_col + i * 4], ap + i * 4);
            #pragma unroll
            for (int i = 0; i < 4; i++) cp_async16(&Bs[b_row * BS_LD + b_col + i * 4], bp + i * 4);
            cp_commit();
        }
    }

    #pragma unroll
    for (int mt = 0; mt < 4; mt++) {
        int r0 = bm + warp_m * 64 + mt * 16 + g;
        #pragma unroll
        for (int nt = 0; nt < 4; nt++) {
            int col = bn + warp_n * 32 + nt * 8 + tg * 2;
            float b0 = bias[col], b1 = bias[col + 1];
            float v00 = acc[mt][nt][0] + b0, v01 = acc[mt][nt][1] + b1;
            float v10 = acc[mt][nt][2] + b0, v11 = acc[mt][nt][3] + b1;
            if (GELU) {
                v00 = 0.5f * v00 * (1.0f + erff(v00 * 0.70710678118654752f));
                v01 = 0.5f * v01 * (1.0f + erff(v01 * 0.70710678118654752f));
                v10 = 0.5f * v10 * (1.0f + erff(v10 * 0.70710678118654752f));
                v11 = 0.5f * v11 * (1.0f + erff(v11 * 0.70710678118654752f));
            }
            if (res) {
                v00 += res[(size_t)r0 * N + col];
                v01 += res[(size_t)r0 * N + col + 1];
                v10 += res[(size_t)(r0 + 8) * N + col];
                v11 += res[(size_t)(r0 + 8) * N + col + 1];
            }
            float2 o0 = {v00, v01}, o1 = {v10, v11};
            *(float2*)(C + (size_t)r0 * N + col) = o0;
            *(float2*)(C + (size_t)(r0 + 8) * N + col) = o1;
        }
    }
}

// ---------------- fused flash attention (tf32 tensor core) ----------------
// block: 128 query rows, 8 warps; KV tiles of 32; HD=64. 3 CTAs/SM.
#define FLD 68
#define VLD 72
#define PLD 36
#define FSMEM_FLOATS (128 * FLD + 32 * FLD + 32 * VLD + 128 * PLD + 32)

template <int CAUSAL>
__global__ __launch_bounds__(256, 1) void flash_kernel(
    const float* __restrict__ Qp, const float* __restrict__ Kp,
    const float* __restrict__ Vp, const unsigned char* __restrict__ mask,
    float* __restrict__ Op, int Sk, int ldq, int ldk, int ldv,
    int qoff, int koff, int voff) {
    extern __shared__ float sm[];
    float* Qs = sm;                  // [128][FLD]
    float* Ks = Qs + 128 * FLD;      // [32][FLD]
    float* Vs = Ks + 32 * FLD;       // [32][VLD]
    float* Ps = Vs + 32 * VLD;       // [128][PLD]
    float* Msk = Ps + 128 * PLD;     // [32]

    int tid = threadIdx.x, warp = tid >> 5, lane = tid & 31;
    int g = lane >> 2, tg = lane & 3;
    int bh = blockIdx.y, b = bh >> 4, h = bh & 15;
    int t0 = blockIdx.x * 128;
    int mrow = warp * 16 + g;

    // load Q tile (fold softmax scale, convert tf32)
    {
        int row = tid >> 1;
        int c0 = (tid & 1) * 32;
        const float* src = Qp + (size_t)(b * TT + t0 + row) * ldq + qoff + h * HD + c0;
        float* dst = Qs + row * FLD + c0;
        #pragma unroll
        for (int i = 0; i < 8; i++) {
            float4 v = *(const float4*)(src + i * 4);
            dst[i * 4 + 0] = tf32r(v.x * 0.125f);
            dst[i * 4 + 1] = tf32r(v.y * 0.125f);
            dst[i * 4 + 2] = tf32r(v.z * 0.125f);
            dst[i * 4 + 3] = tf32r(v.w * 0.125f);
        }
    }

    float m0 = -1e30f, m1 = -1e30f, l0 = 0.f, l1 = 0.f;
    float o[8][4];
    #pragma unroll
    for (int i = 0; i < 8; i++)
        #pragma unroll
        for (int j = 0; j < 4; j++) o[i][j] = 0.f;

    int s_end = CAUSAL ? (t0 + 128 < Sk ? t0 + 128 : Sk) : Sk;
    for (int s0 = 0; s0 < s_end; s0 += 32) {
        __syncthreads();
        // stage K, V (tf32) and mask values
        {
            int row = tid >> 3;            // 0..31
            int c0 = (tid & 7) * 8;        // 2 float4
            const float* ksrc = Kp + (size_t)(b * Sk + s0 + row) * ldk + koff + h * HD + c0;
            const float* vsrc = Vp + (size_t)(b * Sk + s0 + row) * ldv + voff + h * HD + c0;
            float* kd = Ks + row * FLD + c0;
            float* vd = Vs + row * VLD + c0;
            #pragma unroll
            for (int i = 0; i < 2; i++) {
                float4 kv = *(const float4*)(ksrc + i * 4);
                float4 vv = *(const float4*)(vsrc + i * 4);
                kd[i * 4 + 0] = tf32r(kv.x); kd[i * 4 + 1] = tf32r(kv.y);
                kd[i * 4 + 2] = tf32r(kv.z); kd[i * 4 + 3] = tf32r(kv.w);
                vd[i * 4 + 0] = tf32r(vv.x); vd[i * 4 + 1] = tf32r(vv.y);
                vd[i * 4 + 2] = tf32r(vv.z); vd[i * 4 + 3] = tf32r(vv.w);
            }
            if (tid < 32) Msk[tid] = mask[(size_t)b * Sk + s0 + tid] ? -1e30f : 0.f;
        }
        __syncthreads();

        // S = Q K^T (per warp: 16 x 32)
        float s_acc[4][4];
        #pragma unroll
        for (int nt = 0; nt < 4; nt++)
            #pragma unroll
            for (int j = 0; j < 4; j++) s_acc[nt][j] = 0.f;
        #pragma unroll
        for (int kb = 0; kb < 8; kb++) {
            int k0 = kb * 8;
            float af[4];
            af[0] = Qs[mrow * FLD + k0 + tg];
            af[1] = Qs[(mrow + 8) * FLD + k0 + tg];
            af[2] = Qs[mrow * FLD + k0 + tg + 4];
            af[3] = Qs[(mrow + 8) * FLD + k0 + tg + 4];
            #pragma unroll
            for (int nt = 0; nt < 4; nt++) {
                float bf[2];
                bf[0] = Ks[(nt * 8 + g) * FLD + k0 + tg];
                bf[1] = Ks[(nt * 8 + g) * FLD + k0 + tg + 4];
                mma_tf32(s_acc[nt], af, bf);
            }
        }

        // masks
        int r0g = t0 + warp * 16 + g, r1g = r0g + 8;
        bool need_causal = CAUSAL && (s0 + 31 > t0 + warp * 16);
        #pragma unroll
        for (int nt = 0; nt < 4; nt++) {
            int cl = nt * 8 + 2 * tg;
            float mv0 = Msk[cl], mv1 = Msk[cl + 1];
            s_acc[nt][0] += mv0; s_acc[nt][1] += mv1;
            s_acc[nt][2] += mv0; s_acc[nt][3] += mv1;
            if (need_causal) {
                int cg = s0 + cl;
                if (cg > r0g) s_acc[nt][0] = -1e30f;
                if (cg + 1 > r0g) s_acc[nt][1] = -1e30f;
                if (cg > r1g) s_acc[nt][2] = -1e30f;
                if (cg + 1 > r1g) s_acc[nt][3] = -1e30f;
            }
        }

        // online softmax
        float mx0 = -1e30f, mx1 = -1e30f;
        #pragma unroll
        for (int nt = 0; nt < 4; nt++) {
            mx0 = fmaxf(mx0, fmaxf(s_acc[nt][0], s_acc[nt][1]));
            mx1 = fmaxf(mx1, fmaxf(s_acc[nt][2], s_acc[nt][3]));
        }
        mx0 = fmaxf(mx0, __shfl_xor_sync(0xffffffff, mx0, 1));
        mx0 = fmaxf(mx0, __shfl_xor_sync(0xffffffff, mx0, 2));
        mx1 = fmaxf(mx1, __shfl_xor_sync(0xffffffff, mx1, 1));
        mx1 = fmaxf(mx1, __shfl_xor_sync(0xffffffff, mx1, 2));
        float mn0 = fmaxf(m0, mx0), mn1 = fmaxf(m1, mx1);
        float a0 = __expf(m0 - mn0), a1 = __expf(m1 - mn1);
        m0 = mn0; m1 = mn1;

        float rs0 = 0.f, rs1 = 0.f;
        #pragma unroll
        for (int nt = 0; nt < 4; nt++) {
            float p0 = __expf(s_acc[nt][0] - mn0);
            float p1 = __expf(s_acc[nt][1] - mn0);
            float p2 = __expf(s_acc[nt][2] - mn1);
            float p3 = __expf(s_acc[nt][3] - mn1);
            rs0 += p0 + p1; rs1 += p2 + p3;
            int cl = nt * 8 + 2 * tg;
            Ps[mrow * PLD + cl] = tf32r(p0);
            Ps[mrow * PLD + cl + 1] = tf32r(p1);
            Ps[(mrow + 8) * PLD + cl] = tf32r(p2);
            Ps[(mrow + 8) * PLD + cl + 1] = tf32r(p3);
        }
        rs0 += __shfl_xor_sync(0xffffffff, rs0, 1);
        rs0 += __shfl_xor_sync(0xffffffff, rs0, 2);
        rs1 += __shfl_xor_sync(0xffffffff, rs1, 1);
        rs1 += __shfl_xor_sync(0xffffffff, rs1, 2);
        l0 = l0 * a0 + rs0;
        l1 = l1 * a1 + rs1;

        #pragma unroll
        for (int nt = 0; nt < 8; nt++) {
            o[nt][0] *= a0; o[nt][1] *= a0;
            o[nt][2] *= a1; o[nt][3] *= a1;
        }
        __syncwarp();

        // O += P @ V  (k-dim = 32 keys)
        #pragma unroll
        for (int kb = 0; kb < 4; kb++) {
            int k0 = kb * 8;
            float af[4];
            af[0] = Ps[mrow * PLD + k0 + tg];
            af[1] = Ps[(mrow + 8) * PLD + k0 + tg];
            af[2] = Ps[mrow * PLD + k0 + tg + 4];
            af[3] = Ps[(mrow + 8) * PLD + k0 + tg + 4];
            #pragma unroll
            for (int nt = 0; nt < 8; nt++) {
                float bf[2];
                bf[0] = Vs[(k0 + tg) * VLD + nt * 8 + g];
                bf[1] = Vs[(k0 + tg + 4) * VLD + nt * 8 + g];
                mma_tf32(o[nt], af, bf);
            }
        }
    }

    // epilogue: O / l  -> out[b, t, h*64 + d]
    float inv0 = 1.0f / l0, inv1 = 1.0f / l1;
    int row0 = t0 + warp * 16 + g;
    #pragma unroll
    for (int nt = 0; nt < 8; nt++) {
        int col = h * HD + nt * 8 + 2 * tg;
        float2 v0 = {o[nt][0] * inv0, o[nt][1] * inv0};
        float2 v1 = {o[nt][2] * inv1, o[nt][3] * inv1};
        *(float2*)(Op + (size_t)(b * TT + row0) * DDEC + col) = v0;
        *(float2*)(Op + (size_t)(b * TT + row0 + 8) * DDEC + col) = v1;
    }
}

// ---------------- launch ----------------
extern "C" void kernel_launch(void* const* d_in, const int* in_sizes, int n_in,
                              void* d_out, int out_size) {
    (void)in_sizes; (void)n_in; (void)out_size;
    const float* x      = (const float*)d_in[0];
    const float* enc    = (const float*)d_in[1];
    const unsigned char* tgt_mask = (const unsigned char*)d_in[2];
    const unsigned char* enc_mask = (const unsigned char*)d_in[3];
    const float* ln1_w  = (const float*)d_in[4];
    const float* ln1_b  = (const float*)d_in[5];
    const float* qkv_w  = (const float*)d_in[6];
    const float* qkv_b  = (const float*)d_in[7];
    const float* proj_w = (const float*)d_in[8];
    const float* proj_b = (const float*)d_in[9];
    const float* ln2_w  = (const float*)d_in[10];
    const float* ln2_b  = (const float*)d_in[11];
    const float* q_w    = (const float*)d_in[12];
    const float* q_b    = (const float*)d_in[13];
    const float* k_w    = (const float*)d_in[14];
    const float* k_b    = (const float*)d_in[15];
    const float* v_w    = (const float*)d_in[16];
    const float* v_b    = (const float*)d_in[17];
    const float* out_w  = (const float*)d_in[18];
    const float* out_b  = (const float*)d_in[19];
    const float* ln3_w  = (const float*)d_in[20];
    const float* ln3_b  = (const float*)d_in[21];
    const float* mlp1_w = (const float*)d_in[22];
    const float* mlp1_b = (const float*)d_in[23];
    const float* mlp2_w = (const float*)d_in[24];
    const float* mlp2_b = (const float*)d_in[25];
    float* out = (float*)d_out;

    float *h, *qkv, *tmp, *x1, *x2, *kc, *vc, *mlp;
    cudaGetSymbolAddress((void**)&h, g_h);
    cudaGetSymbolAddress((void**)&qkv, g_qkv);
    cudaGetSymbolAddress((void**)&tmp, g_tmp);
    cudaGetSymbolAddress((void**)&x1, g_x1);
    cudaGetSymbolAddress((void**)&x2, g_x2);
    cudaGetSymbolAddress((void**)&kc, g_kc);
    cudaGetSymbolAddress((void**)&vc, g_vc);
    cudaGetSymbolAddress((void**)&mlp, g_mlp);

    const int smem_bytes = SMEM_GEMM * 4;
    const int fsmem_bytes = FSMEM_FLOATS * 4;
    static int attr_set = 0;
    if (!attr_set) {
        cudaFuncSetAttribute(gemm_tf32_kernel<false>,
                             cudaFuncAttributeMaxDynamicSharedMemorySize, smem_bytes);
        cudaFuncSetAttribute(gemm_tf32_kernel<true>,
                             cudaFuncAttributeMaxDynamicSharedMemorySize, smem_bytes);
        cudaFuncSetAttribute(flash_kernel<0>,
                             cudaFuncAttributeMaxDynamicSharedMemorySize, fsmem_bytes);
        cudaFuncSetAttribute(flash_kernel<1>,
                             cudaFuncAttributeMaxDynamicSharedMemorySize, fsmem_bytes);
        attr_set = 1;
    }

    const int M = BB * TT;   // 4096
    const int Me = BB * SS;  // 2304

    // ---- self-attention ----
    ln_kernel<<<M, 256>>>(x, ln1_w, ln1_b, h);
    gemm_tf32_kernel<false><<<dim3(3 * DDEC / 128, M / 128), 256, smem_bytes>>>(h, qkv_w, qkv_b, nullptr, qkv, M, 3 * DDEC, DDEC);
    flash_kernel<1><<<dim3(TT / 128, BB * HH), 256, fsmem_bytes>>>(
        qkv, qkv, qkv, tgt_mask, tmp, TT, 3 * DDEC, 3 * DDEC, 3 * DDEC, 0, DDEC, 2 * DDEC);
    gemm_tf32_kernel<false><<<dim3(DDEC / 128, M / 128), 256, smem_bytes>>>(tmp, proj_w, proj_b, x, x1, M, DDEC, DDEC);

    // ---- cross-attention ----
    ln_kernel<<<M, 256>>>(x1, ln2_w, ln2_b, h);
    gemm_tf32_kernel<false><<<dim3(DDEC / 128, M / 128), 256, smem_bytes>>>(h, q_w, q_b, nullptr, qkv, M, DDEC, DDEC);
    gemm_tf32_kernel<false><<<dim3(DDEC / 128, Me / 128), 256, smem_bytes>>>(enc, k_w, k_b, nullptr, kc, Me, DDEC, 768);
    gemm_tf32_kernel<false><<<dim3(DDEC / 128, Me / 128), 256, smem_bytes>>>(enc, v_w, v_b, nullptr, vc, Me, DDEC, 768);
    flash_kernel<0><<<dim3(TT / 128, BB * HH), 256, fsmem_bytes>>>(
        qkv, kc, vc, enc_mask, tmp, SS, DDEC, DDEC, DDEC, 0, 0, 0);
    gemm_tf32_kernel<false><<<dim3(DDEC / 128, M / 128), 256, smem_bytes>>>(tmp, out_w, out_b, x1, x2, M, DDEC, DDEC);

    // ---- MLP ----
    ln_kernel<<<M, 256>>>(x2, ln3_w, ln3_b, h);
    gemm_tf32_kernel<true><<<dim3(DMLP / 128, M / 128), 256, smem_bytes>>>(h, mlp1_w, mlp1_b, nullptr, mlp, M, DMLP, DDEC);
    gemm_tf32_kernel<false><<<dim3(DDEC / 128, M / 128), 256, smem_bytes>>>(mlp, mlp2_w, mlp2_b, x2, out, M, DDEC, DMLP);
}

// round 5
// speedup vs baseline: 1.0068x; 1.0068x over previous
#include <cuda_runtime.h>
#include <math.h>
#include <stdint.h>

#define BB 4
#define TT 1024
#define SS 576
#define HH 16
#define HD 64
#define DDEC 1024
#define DMLP 4096

// ---------------- scratch (device globals; no allocation allowed) ----------------
__device__ float g_h[4194304];        // LN output        [4096,1024] (tf32-rounded)
__device__ float g_qkv[12582912];     // qkv [4096,3072] / reused as q  [4096,1024]
__device__ float g_tmp[4194304];      // sa / ca          [4096,1024] (tf32-rounded)
__device__ float g_x1[4194304];
__device__ float g_x2[4194304];
__device__ float g_kc[2359296];       // cross K          [2304,1024]
__device__ float g_vc[2359296];       // cross V          [2304,1024]
__device__ float g_mlp[16777216];     // mlp hidden       [4096,4096] (tf32-rounded)
__device__ float g_wr[18022400];      // tf32-rounded weights + enc

// ---------------- tf32 / async helpers ----------------
__device__ __forceinline__ float tf32r(float x) {
    uint32_t u;
    asm("cvt.rna.tf32.f32 %0, %1;" : "=r"(u) : "f"(x));
    return __uint_as_float(u);
}

__device__ __forceinline__ void mma_tf32(float (&d)[4], const float (&a)[4], const float (&b)[2]) {
    asm volatile(
        "mma.sync.aligned.m16n8k8.row.col.f32.tf32.tf32.f32 "
        "{%0,%1,%2,%3}, {%4,%5,%6,%7}, {%8,%9}, {%0,%1,%2,%3};"
        : "+f"(d[0]), "+f"(d[1]), "+f"(d[2]), "+f"(d[3])
        : "r"(__float_as_uint(a[0])), "r"(__float_as_uint(a[1])),
          "r"(__float_as_uint(a[2])), "r"(__float_as_uint(a[3])),
          "r"(__float_as_uint(b[0])), "r"(__float_as_uint(b[1])));
}

__device__ __forceinline__ void cp_async16(void* sdst, const void* gsrc) {
    uint32_t sa = (uint32_t)__cvta_generic_to_shared(sdst);
    asm volatile("cp.async.cg.shared.global [%0], [%1], 16;" :: "r"(sa), "l"(gsrc));
}
__device__ __forceinline__ void cp_commit() { asm volatile("cp.async.commit_group;"); }
template <int N>
__device__ __forceinline__ void cp_wait() { asm volatile("cp.async.wait_group %0;" :: "n"(N)); }

// ---------------- round fp32 -> tf32(RNA) elementwise ----------------
__global__ void round_kernel(const float* __restrict__ src, float* __restrict__ dst, int n4) {
    int i = blockIdx.x * 256 + threadIdx.x;
    if (i < n4) {
        float4 v = ((const float4*)src)[i];
        v.x = tf32r(v.x); v.y = tf32r(v.y); v.z = tf32r(v.z); v.w = tf32r(v.w);
        ((float4*)dst)[i] = v;
    }
}

// ---------------- LayerNorm: one block per row of 1024 (output tf32-rounded) ----------------
__global__ void ln_kernel(const float* __restrict__ x, const float* __restrict__ w,
                          const float* __restrict__ b, float* __restrict__ out) {
    __shared__ float red[256];
    int row = blockIdx.x, tid = threadIdx.x;
    const float4* xr = (const float4*)(x + (size_t)row * DDEC);
    float4 v = xr[tid];
    red[tid] = v.x + v.y + v.z + v.w;
    __syncthreads();
    #pragma unroll
    for (int o = 128; o > 0; o >>= 1) { if (tid < o) red[tid] += red[tid + o]; __syncthreads(); }
    float mean = red[0] * (1.0f / 1024.0f);
    __syncthreads();
    float dx = v.x - mean, dy = v.y - mean, dz = v.z - mean, dw = v.w - mean;
    red[tid] = dx * dx + dy * dy + dz * dz + dw * dw;
    __syncthreads();
    #pragma unroll
    for (int o = 128; o > 0; o >>= 1) { if (tid < o) red[tid] += red[tid + o]; __syncthreads(); }
    float rstd = rsqrtf(red[0] * (1.0f / 1024.0f) + 1e-5f);
    float4 wv = ((const float4*)w)[tid];
    float4 bv = ((const float4*)b)[tid];
    float4 o4;
    o4.x = tf32r(dx * rstd * wv.x + bv.x);
    o4.y = tf32r(dy * rstd * wv.y + bv.y);
    o4.z = tf32r(dz * rstd * wv.z + bv.z);
    o4.w = tf32r(dw * rstd * wv.w + bv.w);
    ((float4*)(out + (size_t)row * DDEC))[tid] = o4;
}

// ---------------- tf32 tensor GEMM (operands pre-rounded; no cvt inside) ----------------
// block 128x128x32, 8 warps, 3-stage cp.async pipeline
#define AS_LD 36
#define BS_LD 132
#define G_STAGE (128 * AS_LD + 32 * BS_LD)    // 8832 floats per stage
#define SMEM_GEMM (3 * G_STAGE)

template <bool GELU>
__global__ __launch_bounds__(256, 2) void gemm_tf32_kernel(
    const float* __restrict__ A, const float* __restrict__ W,
    const float* __restrict__ bias, const float* __restrict__ res,
    float* __restrict__ C, int M, int N, int K) {
    extern __shared__ float smem[];

    int tid = threadIdx.x;
    int warp = tid >> 5, lane = tid & 31;
    int warp_m = warp >> 2, warp_n = warp & 3;
    int g = lane >> 2, tg = lane & 3;
    int bm = blockIdx.y * 128, bn = blockIdx.x * 128;

    int a_row = tid >> 1, a_col = (tid & 1) * 16;   // 4x float4 per thread
    int b_row = tid >> 3, b_col = (tid & 7) * 16;   // 4x float4 per thread
    const float* Ag = A + (size_t)(bm + a_row) * K + a_col;
    const float* Wg = W + (size_t)b_row * N + bn + b_col;

    float acc[4][4][4];
    #pragma unroll
    for (int i = 0; i < 4; i++)
        #pragma unroll
        for (int j = 0; j < 4; j++)
            #pragma unroll
            for (int c = 0; c < 4; c++) acc[i][j][c] = 0.f;

    int kTiles = K >> 5;

    #pragma unroll
    for (int s = 0; s < 2; s++) {
        float* As = smem + s * G_STAGE;
        float* Bs = As + 128 * AS_LD;
        const float* ap = Ag + s * 32;
        const float* bp = Wg + (size_t)(s * 32) * N;
        #pragma unroll
        for (int i = 0; i < 4; i++) cp_async16(&As[a_row * AS_LD + a_col + i * 4], ap + i * 4);
        #pragma unroll
        for (int i = 0; i < 4; i++) cp_async16(&Bs[b_row * BS_LD + b_col + i * 4], bp + i * 4);
        cp_commit();
    }

    for (int kt = 0; kt < kTiles; kt++) {
        cp_wait<1>();
        __syncthreads();
        int buf = kt % 3;
        float* Ab = smem + buf * G_STAGE;
        float* Bb = Ab + 128 * AS_LD;

        #pragma unroll
        for (int kk = 0; kk < 4; kk++) {
            int kb = kk << 3;
            float af[4][4], bf[4][2];
            #pragma unroll
            for (int mt = 0; mt < 4; mt++) {
                int m0 = warp_m * 64 + mt * 16 + g;
                af[mt][0] = Ab[m0 * AS_LD + kb + tg];
                af[mt][1] = Ab[(m0 + 8) * AS_LD + kb + tg];
                af[mt][2] = Ab[m0 * AS_LD + kb + tg + 4];
                af[mt][3] = Ab[(m0 + 8) * AS_LD + kb + tg + 4];
            }
            #pragma unroll
            for (int nt = 0; nt < 4; nt++) {
                int n0 = warp_n * 32 + nt * 8 + g;
                bf[nt][0] = Bb[(kb + tg) * BS_LD + n0];
                bf[nt][1] = Bb[(kb + tg + 4) * BS_LD + n0];
            }
            #pragma unroll
            for (int mt = 0; mt < 4; mt++)
                #pragma unroll
                for (int nt = 0; nt < 4; nt++) mma_tf32(acc[mt][nt], af[mt], bf[nt]);
        }

        int ktn = kt + 2;
        if (ktn < kTiles) {
            float* As = smem + (ktn % 3) * G_STAGE;
            float* Bs = As + 128 * AS_LD;
            const float* ap = Ag + ktn * 32;
            const float* bp = Wg + (size_t)(ktn * 32) * N;
            #pragma unroll
            for (int i = 0; i < 4; i++) cp_async16(&As[a_row * AS_LD + a_col + i * 4], ap + i * 4);
            #pragma unroll
            for (int i = 0; i < 4; i++) cp_async16(&Bs[b_row * BS_LD + b_col + i * 4], bp + i * 4);
            cp_commit();
        }
    }

    #pragma unroll
    for (int mt = 0; mt < 4; mt++) {
        int r0 = bm + warp_m * 64 + mt * 16 + g;
        #pragma unroll
        for (int nt = 0; nt < 4; nt++) {
            int col = bn + warp_n * 32 + nt * 8 + tg * 2;
            float b0 = bias[col], b1 = bias[col + 1];
            float v00 = acc[mt][nt][0] + b0, v01 = acc[mt][nt][1] + b1;
            float v10 = acc[mt][nt][2] + b0, v11 = acc[mt][nt][3] + b1;
            if (GELU) {
                // GELU output feeds another GEMM as A operand -> round to tf32
                v00 = tf32r(0.5f * v00 * (1.0f + erff(v00 * 0.70710678118654752f)));
                v01 = tf32r(0.5f * v01 * (1.0f + erff(v01 * 0.70710678118654752f)));
                v10 = tf32r(0.5f * v10 * (1.0f + erff(v10 * 0.70710678118654752f)));
                v11 = tf32r(0.5f * v11 * (1.0f + erff(v11 * 0.70710678118654752f)));
            }
            if (res) {
                v00 += res[(size_t)r0 * N + col];
                v01 += res[(size_t)r0 * N + col + 1];
                v10 += res[(size_t)(r0 + 8) * N + col];
                v11 += res[(size_t)(r0 + 8) * N + col + 1];
            }
            float2 o0 = {v00, v01}, o1 = {v10, v11};
            *(float2*)(C + (size_t)r0 * N + col) = o0;
            *(float2*)(C + (size_t)(r0 + 8) * N + col) = o1;
        }
    }
}

// ---------------- fused flash attention (tf32 tensor core; R3 config) ----------------
#define FLD 68
#define FSMEM_FLOATS (128 * FLD + 64 * FLD + 64 * FLD + 128 * FLD + 64)

template <int CAUSAL>
__global__ __launch_bounds__(256, 1) void flash_kernel(
    const float* __restrict__ Qp, const float* __restrict__ Kp,
    const float* __restrict__ Vp, const unsigned char* __restrict__ mask,
    float* __restrict__ Op, int Sk, int ldq, int ldk, int ldv,
    int qoff, int koff, int voff) {
    extern __shared__ float sm[];
    float* Qs = sm;                 // [128][FLD]
    float* Ks = Qs + 128 * FLD;     // [64][FLD]
    float* Vs = Ks + 64 * FLD;      // [64][FLD]
    float* Ps = Vs + 64 * FLD;      // [128][FLD]
    float* Msk = Ps + 128 * FLD;    // [64]

    int tid = threadIdx.x, warp = tid >> 5, lane = tid & 31;
    int g = lane >> 2, tg = lane & 3;
    int bh = blockIdx.y, b = bh >> 4, h = bh & 15;
    int t0 = blockIdx.x * 128;
    int mrow = warp * 16 + g;

    {
        int row = tid >> 1;
        int c0 = (tid & 1) * 32;
        const float* src = Qp + (size_t)(b * TT + t0 + row) * ldq + qoff + h * HD + c0;
        float* dst = Qs + row * FLD + c0;
        #pragma unroll
        for (int i = 0; i < 8; i++) {
            float4 v = *(const float4*)(src + i * 4);
            dst[i * 4 + 0] = tf32r(v.x * 0.125f);
            dst[i * 4 + 1] = tf32r(v.y * 0.125f);
            dst[i * 4 + 2] = tf32r(v.z * 0.125f);
            dst[i * 4 + 3] = tf32r(v.w * 0.125f);
        }
    }

    float m0 = -1e30f, m1 = -1e30f, l0 = 0.f, l1 = 0.f;
    float o[8][4];
    #pragma unroll
    for (int i = 0; i < 8; i++)
        #pragma unroll
        for (int j = 0; j < 4; j++) o[i][j] = 0.f;

    int s_end = CAUSAL ? (t0 + 128 < Sk ? t0 + 128 : Sk) : Sk;
    for (int s0 = 0; s0 < s_end; s0 += 64) {
        __syncthreads();
        {
            int row = tid >> 2;
            int c0 = (tid & 3) * 16;
            const float* ksrc = Kp + (size_t)(b * Sk + s0 + row) * ldk + koff + h * HD + c0;
            const float* vsrc = Vp + (size_t)(b * Sk + s0 + row) * ldv + voff + h * HD + c0;
            float* kd = Ks + row * FLD + c0;
            float* vd = Vs + row * FLD + c0;
            #pragma unroll
            for (int i = 0; i < 4; i++) {
                float4 kv = *(const float4*)(ksrc + i * 4);
                float4 vv = *(const float4*)(vsrc + i * 4);
                kd[i * 4 + 0] = tf32r(kv.x); kd[i * 4 + 1] = tf32r(kv.y);
                kd[i * 4 + 2] = tf32r(kv.z); kd[i * 4 + 3] = tf32r(kv.w);
                vd[i * 4 + 0] = tf32r(vv.x); vd[i * 4 + 1] = tf32r(vv.y);
                vd[i * 4 + 2] = tf32r(vv.z); vd[i * 4 + 3] = tf32r(vv.w);
            }
            if (tid < 64) Msk[tid] = mask[(size_t)b * Sk + s0 + tid] ? -1e30f : 0.f;
        }
        __syncthreads();

        float s_acc[8][4];
        #pragma unroll
        for (int nt = 0; nt < 8; nt++)
            #pragma unroll
            for (int j = 0; j < 4; j++) s_acc[nt][j] = 0.f;
        #pragma unroll
        for (int kb = 0; kb < 8; kb++) {
            int k0 = kb * 8;
            float af[4];
            af[0] = Qs[mrow * FLD + k0 + tg];
            af[1] = Qs[(mrow + 8) * FLD + k0 + tg];
            af[2] = Qs[mrow * FLD + k0 + tg + 4];
            af[3] = Qs[(mrow + 8) * FLD + k0 + tg + 4];
            #pragma unroll
            for (int nt = 0; nt < 8; nt++) {
                float bf[2];
                bf[0] = Ks[(nt * 8 + g) * FLD + k0 + tg];
                bf[1] = Ks[(nt * 8 + g) * FLD + k0 + tg + 4];
                mma_tf32(s_acc[nt], af, bf);
            }
        }

        int r0g = t0 + warp * 16 + g, r1g = r0g + 8;
        bool need_causal = CAUSAL && (s0 + 63 > t0 + warp * 16);
        #pragma unroll
        for (int nt = 0; nt < 8; nt++) {
            int cl = nt * 8 + 2 * tg;
            float mv0 = Msk[cl], mv1 = Msk[cl + 1];
            s_acc[nt][0] += mv0; s_acc[nt][1] += mv1;
            s_acc[nt][2] += mv0; s_acc[nt][3] += mv1;
            if (need_causal) {
                int cg = s0 + cl;
                if (cg > r0g) s_acc[nt][0] = -1e30f;
                if (cg + 1 > r0g) s_acc[nt][1] = -1e30f;
                if (cg > r1g) s_acc[nt][2] = -1e30f;
                if (cg + 1 > r1g) s_acc[nt][3] = -1e30f;
            }
        }

        float mx0 = -1e30f, mx1 = -1e30f;
        #pragma unroll
        for (int nt = 0; nt < 8; nt++) {
            mx0 = fmaxf(mx0, fmaxf(s_acc[nt][0], s_acc[nt][1]));
            mx1 = fmaxf(mx1, fmaxf(s_acc[nt][2], s_acc[nt][3]));
        }
        mx0 = fmaxf(mx0, __shfl_xor_sync(0xffffffff, mx0, 1));
        mx0 = fmaxf(mx0, __shfl_xor_sync(0xffffffff, mx0, 2));
        mx1 = fmaxf(mx1, __shfl_xor_sync(0xffffffff, mx1, 1));
        mx1 = fmaxf(mx1, __shfl_xor_sync(0xffffffff, mx1, 2));
        float mn0 = fmaxf(m0, mx0), mn1 = fmaxf(m1, mx1);
        float a0 = __expf(m0 - mn0), a1 = __expf(m1 - mn1);
        m0 = mn0; m1 = mn1;

        float rs0 = 0.f, rs1 = 0.f;
        #pragma unroll
        for (int nt = 0; nt < 8; nt++) {
            float p0 = __expf(s_acc[nt][0] - mn0);
            float p1 = __expf(s_acc[nt][1] - mn0);
            float p2 = __expf(s_acc[nt][2] - mn1);
            float p3 = __expf(s_acc[nt][3] - mn1);
            rs0 += p0 + p1; rs1 += p2 + p3;
            int cl = nt * 8 + 2 * tg;
            Ps[mrow * FLD + cl] = tf32r(p0);
            Ps[mrow * FLD + cl + 1] = tf32r(p1);
            Ps[(mrow + 8) * FLD + cl] = tf32r(p2);
            Ps[(mrow + 8) * FLD + cl + 1] = tf32r(p3);
        }
        rs0 += __shfl_xor_sync(0xffffffff, rs0, 1);
        rs0 += __shfl_xor_sync(0xffffffff, rs0, 2);
        rs1 += __shfl_xor_sync(0xffffffff, rs1, 1);
        rs1 += __shfl_xor_sync(0xffffffff, rs1, 2);
        l0 = l0 * a0 + rs0;
        l1 = l1 * a1 + rs1;

        #pragma unroll
        for (int nt = 0; nt < 8; nt++) {
            o[nt][0] *= a0; o[nt][1] *= a0;
            o[nt][2] *= a1; o[nt][3] *= a1;
        }
        __syncwarp();

        #pragma unroll
        for (int kb = 0; kb < 8; kb++) {
            int k0 = kb * 8;
            float af[4];
            af[0] = Ps[mrow * FLD + k0 + tg];
            af[1] = Ps[(mrow + 8) * FLD + k0 + tg];
            af[2] = Ps[mrow * FLD + k0 + tg + 4];
            af[3] = Ps[(mrow + 8) * FLD + k0 + tg + 4];
            #pragma unroll
            for (int nt = 0; nt < 8; nt++) {
                float bf[2];
                bf[0] = Vs[(k0 + tg) * FLD + nt * 8 + g];
                bf[1] = Vs[(k0 + tg + 4) * FLD + nt * 8 + g];
                mma_tf32(o[nt], af, bf);
            }
        }
    }

    // epilogue: O / l, rounded to tf32 (feeds proj/out GEMM as A operand)
    float inv0 = 1.0f / l0, inv1 = 1.0f / l1;
    int row0 = t0 + warp * 16 + g;
    #pragma unroll
    for (int nt = 0; nt < 8; nt++) {
        int col = h * HD + nt * 8 + 2 * tg;
        float2 v0 = {tf32r(o[nt][0] * inv0), tf32r(o[nt][1] * inv0)};
        float2 v1 = {tf32r(o[nt][2] * inv1), tf32r(o[nt][3] * inv1)};
        *(float2*)(Op + (size_t)(b * TT + row0) * DDEC + col) = v0;
        *(float2*)(Op + (size_t)(b * TT + row0 + 8) * DDEC + col) = v1;
    }
}

// ---------------- launch ----------------
extern "C" void kernel_launch(void* const* d_in, const int* in_sizes, int n_in,
                              void* d_out, int out_size) {
    (void)in_sizes; (void)n_in; (void)out_size;
    const float* x      = (const float*)d_in[0];
    const float* enc    = (const float*)d_in[1];
    const unsigned char* tgt_mask = (const unsigned char*)d_in[2];
    const unsigned char* enc_mask = (const unsigned char*)d_in[3];
    const float* ln1_w  = (const float*)d_in[4];
    const float* ln1_b  = (const float*)d_in[5];
    const float* qkv_w  = (const float*)d_in[6];
    const float* qkv_b  = (const float*)d_in[7];
    const float* proj_w = (const float*)d_in[8];
    const float* proj_b = (const float*)d_in[9];
    const float* ln2_w  = (const float*)d_in[10];
    const float* ln2_b  = (const float*)d_in[11];
    const float* q_w    = (const float*)d_in[12];
    const float* q_b    = (const float*)d_in[13];
    const float* k_w    = (const float*)d_in[14];
    const float* k_b    = (const float*)d_in[15];
    const float* v_w    = (const float*)d_in[16];
    const float* v_b    = (const float*)d_in[17];
    const float* out_w  = (const float*)d_in[18];
    const float* out_b  = (const float*)d_in[19];
    const float* ln3_w  = (const float*)d_in[20];
    const float* ln3_b  = (const float*)d_in[21];
    const float* mlp1_w = (const float*)d_in[22];
    const float* mlp1_b = (const float*)d_in[23];
    const float* mlp2_w = (const float*)d_in[24];
    const float* mlp2_b = (const float*)d_in[25];
    float* out = (float*)d_out;

    float *h, *qkv, *tmp, *x1, *x2, *kc, *vc, *mlp, *wr;
    cudaGetSymbolAddress((void**)&h, g_h);
    cudaGetSymbolAddress((void**)&qkv, g_qkv);
    cudaGetSymbolAddress((void**)&tmp, g_tmp);
    cudaGetSymbolAddress((void**)&x1, g_x1);
    cudaGetSymbolAddress((void**)&x2, g_x2);
    cudaGetSymbolAddress((void**)&kc, g_kc);
    cudaGetSymbolAddress((void**)&vc, g_vc);
    cudaGetSymbolAddress((void**)&mlp, g_mlp);
    cudaGetSymbolAddress((void**)&wr, g_wr);

    // rounded weight/enc layout in g_wr
    float* r_qkv_w  = wr;
    float* r_proj_w = wr + 3145728;
    float* r_q_w    = wr + 4194304;
    float* r_k_w    = wr + 5242880;
    float* r_v_w    = wr + 6029312;
    float* r_out_w  = wr + 6815744;
    float* r_mlp1_w = wr + 7864320;
    float* r_mlp2_w = wr + 12058624;
    float* r_enc    = wr + 16252928;

    const int smem_bytes = SMEM_GEMM * 4;
    const int fsmem_bytes = FSMEM_FLOATS * 4;
    static int attr_set = 0;
    if (!attr_set) {
        cudaFuncSetAttribute(gemm_tf32_kernel<false>,
                             cudaFuncAttributeMaxDynamicSharedMemorySize, smem_bytes);
        cudaFuncSetAttribute(gemm_tf32_kernel<true>,
                             cudaFuncAttributeMaxDynamicSharedMemorySize, smem_bytes);
        cudaFuncSetAttribute(flash_kernel<0>,
                             cudaFuncAttributeMaxDynamicSharedMemorySize, fsmem_bytes);
        cudaFuncSetAttribute(flash_kernel<1>,
                             cudaFuncAttributeMaxDynamicSharedMemorySize, fsmem_bytes);
        attr_set = 1;
    }

    const int M = BB * TT;   // 4096
    const int Me = BB * SS;  // 2304

    // ---- pre-round weights + enc to tf32 ----
    auto rr = [](const float* s, float* d, int n) {
        round_kernel<<<(n / 4 + 255) / 256, 256>>>(s, d, n / 4);
    };
    rr(qkv_w, r_qkv_w, 3145728);
    rr(proj_w, r_proj_w, 1048576);
    rr(q_w, r_q_w, 1048576);
    rr(k_w, r_k_w, 786432);
    rr(v_w, r_v_w, 786432);
    rr(out_w, r_out_w, 1048576);
    rr(mlp1_w, r_mlp1_w, 4194304);
    rr(mlp2_w, r_mlp2_w, 4194304);
    rr(enc, r_enc, 1769472);

    // ---- self-attention ----
    ln_kernel<<<M, 256>>>(x, ln1_w, ln1_b, h);
    gemm_tf32_kernel<false><<<dim3(3 * DDEC / 128, M / 128), 256, smem_bytes>>>(h, r_qkv_w, qkv_b, nullptr, qkv, M, 3 * DDEC, DDEC);
    flash_kernel<1><<<dim3(TT / 128, BB * HH), 256, fsmem_bytes>>>(
        qkv, qkv, qkv, tgt_mask, tmp, TT, 3 * DDEC, 3 * DDEC, 3 * DDEC, 0, DDEC, 2 * DDEC);
    gemm_tf32_kernel<false><<<dim3(DDEC / 128, M / 128), 256, smem_bytes>>>(tmp, r_proj_w, proj_b, x, x1, M, DDEC, DDEC);

    // ---- cross-attention ----
    ln_kernel<<<M, 256>>>(x1, ln2_w, ln2_b, h);
    gemm_tf32_kernel<false><<<dim3(DDEC / 128, M / 128), 256, smem_bytes>>>(h, r_q_w, q_b, nullptr, qkv, M, DDEC, DDEC);
    gemm_tf32_kernel<false><<<dim3(DDEC / 128, Me / 128), 256, smem_bytes>>>(r_enc, r_k_w, k_b, nullptr, kc, Me, DDEC, 768);
    gemm_tf32_kernel<false><<<dim3(DDEC / 128, Me / 128), 256, smem_bytes>>>(r_enc, r_v_w, v_b, nullptr, vc, Me, DDEC, 768);
    flash_kernel<0><<<dim3(TT / 128, BB * HH), 256, fsmem_bytes>>>(
        qkv, kc, vc, enc_mask, tmp, SS, DDEC, DDEC, DDEC, 0, 0, 0);
    gemm_tf32_kernel<false><<<dim3(DDEC / 128, M / 128), 256, smem_bytes>>>(tmp, r_out_w, out_b, x1, x2, M, DDEC, DDEC);

    // ---- MLP ----
    ln_kernel<<<M, 256>>>(x2, ln3_w, ln3_b, h);
    gemm_tf32_kernel<true><<<dim3(DMLP / 128, M / 128), 256, smem_bytes>>>(h, r_mlp1_w, mlp1_b, nullptr, mlp, M, DMLP, DDEC);
    gemm_tf32_kernel<false><<<dim3(DDEC / 128, M / 128), 256, smem_bytes>>>(mlp, r_mlp2_w, mlp2_b, x2, out, M, DDEC, DMLP);
}

// round 6
// speedup vs baseline: 1.1108x; 1.1033x over previous
#include <cuda_runtime.h>
#include <math.h>
#include <stdint.h>

#define BB 4
#define TT 1024
#define SS 576
#define HH 16
#define HD 64
#define DDEC 1024
#define DMLP 4096

// ---------------- scratch (device globals; no allocation allowed) ----------------
__device__ float g_h[4194304];        // LN output        [4096,1024]
__device__ float g_qkv[12582912];     // qkv [4096,3072] / reused as q  [4096,1024]
__device__ float g_tmp[4194304];      // sa / ca          [4096,1024]
__device__ float g_x1[4194304];
__device__ float g_x2[4194304];
__device__ float g_kc[2359296];       // cross K          [2304,1024]
__device__ float g_vc[2359296];       // cross V          [2304,1024]
__device__ float g_mlp[16777216];     // mlp hidden       [4096,4096]

// ---------------- LayerNorm: one block per row of 1024 ----------------
__global__ void ln_kernel(const float* __restrict__ x, const float* __restrict__ w,
                          const float* __restrict__ b, float* __restrict__ out) {
    __shared__ float red[256];
    int row = blockIdx.x, tid = threadIdx.x;
    const float4* xr = (const float4*)(x + (size_t)row * DDEC);
    float4 v = xr[tid];
    red[tid] = v.x + v.y + v.z + v.w;
    __syncthreads();
    #pragma unroll
    for (int o = 128; o > 0; o >>= 1) { if (tid < o) red[tid] += red[tid + o]; __syncthreads(); }
    float mean = red[0] * (1.0f / 1024.0f);
    __syncthreads();
    float dx = v.x - mean, dy = v.y - mean, dz = v.z - mean, dw = v.w - mean;
    red[tid] = dx * dx + dy * dy + dz * dz + dw * dw;
    __syncthreads();
    #pragma unroll
    for (int o = 128; o > 0; o >>= 1) { if (tid < o) red[tid] += red[tid + o]; __syncthreads(); }
    float rstd = rsqrtf(red[0] * (1.0f / 1024.0f) + 1e-5f);
    float4 wv = ((const float4*)w)[tid];
    float4 bv = ((const float4*)b)[tid];
    float4 o4;
    o4.x = dx * rstd * wv.x + bv.x;
    o4.y = dy * rstd * wv.y + bv.y;
    o4.z = dz * rstd * wv.z + bv.z;
    o4.w = dw * rstd * wv.w + bv.w;
    ((float4*)(out + (size_t)row * DDEC))[tid] = o4;
}

// ---------------- tf32 helpers ----------------
__device__ __forceinline__ float tf32r(float x) {
    uint32_t u;
    asm("cvt.rna.tf32.f32 %0, %1;" : "=r"(u) : "f"(x));
    return __uint_as_float(u);
}

__device__ __forceinline__ void mma_tf32(float (&d)[4], const float (&a)[4], const float (&b)[2]) {
    asm volatile(
        "mma.sync.aligned.m16n8k8.row.col.f32.tf32.tf32.f32 "
        "{%0,%1,%2,%3}, {%4,%5,%6,%7}, {%8,%9}, {%0,%1,%2,%3};"
        : "+f"(d[0]), "+f"(d[1]), "+f"(d[2]), "+f"(d[3])
        : "r"(__float_as_uint(a[0])), "r"(__float_as_uint(a[1])),
          "r"(__float_as_uint(a[2])), "r"(__float_as_uint(a[3])),
          "r"(__float_as_uint(b[0])), "r"(__float_as_uint(b[1])));
}

// ---------------- tf32 tensor GEMM (R3 version: cvt at smem store) ----------------
// block tile 128x128x32, 8 warps (2x4), warp tile 64x32 via m16n8k8
#define AS_LD 36
#define BS_LD 132
#define SMEM_GEMM (2 * 128 * AS_LD + 2 * 32 * BS_LD)  // floats

template <bool GELU>
__global__ __launch_bounds__(256, 1) void gemm_tf32_kernel(
    const float* __restrict__ A, const float* __restrict__ W,
    const float* __restrict__ bias, const float* __restrict__ res,
    float* __restrict__ C, int M, int N, int K) {
    extern __shared__ float smem[];
    float* As = smem;                     // [2][128][AS_LD]
    float* Bs = smem + 2 * 128 * AS_LD;   // [2][32][BS_LD]

    int tid = threadIdx.x;
    int warp = tid >> 5, lane = tid & 31;
    int warp_m = warp >> 2, warp_n = warp & 3;
    int g = lane >> 2, tg = lane & 3;
    int bm = blockIdx.y * 128, bn = blockIdx.x * 128;

    int a_row = tid >> 3, a_c4 = (tid & 7) << 2;
    int b_row = tid >> 5, b_c4 = (tid & 31) << 2;

    float acc[4][4][4];
    #pragma unroll
    for (int i = 0; i < 4; i++)
        #pragma unroll
        for (int j = 0; j < 4; j++)
            #pragma unroll
            for (int c = 0; c < 4; c++) acc[i][j][c] = 0.f;

    #pragma unroll
    for (int i = 0; i < 4; i++) {
        int row = a_row + i * 32;
        float4 v = *(const float4*)(A + (size_t)(bm + row) * K + a_c4);
        float* dst = As + row * AS_LD + a_c4;
        dst[0] = tf32r(v.x); dst[1] = tf32r(v.y); dst[2] = tf32r(v.z); dst[3] = tf32r(v.w);
    }
    #pragma unroll
    for (int i = 0; i < 4; i++) {
        int row = b_row + i * 8;
        float4 v = *(const float4*)(W + (size_t)row * N + bn + b_c4);
        float* dst = Bs + row * BS_LD + b_c4;
        dst[0] = tf32r(v.x); dst[1] = tf32r(v.y); dst[2] = tf32r(v.z); dst[3] = tf32r(v.w);
    }
    __syncthreads();

    int kTiles = K >> 5;
    for (int kt = 0; kt < kTiles; kt++) {
        int buf = kt & 1;
        float* Ab = As + buf * 128 * AS_LD;
        float* Bb = Bs + buf * 32 * BS_LD;
        bool pre = (kt + 1) < kTiles;
        float4 pa[4], pb[4];
        if (pre) {
            int k0 = (kt + 1) << 5;
            #pragma unroll
            for (int i = 0; i < 4; i++)
                pa[i] = *(const float4*)(A + (size_t)(bm + a_row + i * 32) * K + k0 + a_c4);
            #pragma unroll
            for (int i = 0; i < 4; i++)
                pb[i] = *(const float4*)(W + (size_t)(k0 + b_row + i * 8) * N + bn + b_c4);
        }

        #pragma unroll
        for (int kk = 0; kk < 4; kk++) {
            int kb = kk << 3;
            float af[4][4], bf[4][2];
            #pragma unroll
            for (int mt = 0; mt < 4; mt++) {
                int m0 = warp_m * 64 + mt * 16 + g;
                af[mt][0] = Ab[m0 * AS_LD + kb + tg];
                af[mt][1] = Ab[(m0 + 8) * AS_LD + kb + tg];
                af[mt][2] = Ab[m0 * AS_LD + kb + tg + 4];
                af[mt][3] = Ab[(m0 + 8) * AS_LD + kb + tg + 4];
            }
            #pragma unroll
            for (int nt = 0; nt < 4; nt++) {
                int n0 = warp_n * 32 + nt * 8 + g;
                bf[nt][0] = Bb[(kb + tg) * BS_LD + n0];
                bf[nt][1] = Bb[(kb + tg + 4) * BS_LD + n0];
            }
            #pragma unroll
            for (int mt = 0; mt < 4; mt++)
                #pragma unroll
                for (int nt = 0; nt < 4; nt++) mma_tf32(acc[mt][nt], af[mt], bf[nt]);
        }

        if (pre) {
            float* Abn = As + (buf ^ 1) * 128 * AS_LD;
            float* Bbn = Bs + (buf ^ 1) * 32 * BS_LD;
            #pragma unroll
            for (int i = 0; i < 4; i++) {
                float* dst = Abn + (a_row + i * 32) * AS_LD + a_c4;
                dst[0] = tf32r(pa[i].x); dst[1] = tf32r(pa[i].y);
                dst[2] = tf32r(pa[i].z); dst[3] = tf32r(pa[i].w);
            }
            #pragma unroll
            for (int i = 0; i < 4; i++) {
                float* dst = Bbn + (b_row + i * 8) * BS_LD + b_c4;
                dst[0] = tf32r(pb[i].x); dst[1] = tf32r(pb[i].y);
                dst[2] = tf32r(pb[i].z); dst[3] = tf32r(pb[i].w);
            }
        }
        __syncthreads();
    }

    #pragma unroll
    for (int mt = 0; mt < 4; mt++) {
        int r0 = bm + warp_m * 64 + mt * 16 + g;
        #pragma unroll
        for (int nt = 0; nt < 4; nt++) {
            int col = bn + warp_n * 32 + nt * 8 + tg * 2;
            float b0 = bias[col], b1 = bias[col + 1];
            float v00 = acc[mt][nt][0] + b0, v01 = acc[mt][nt][1] + b1;
            float v10 = acc[mt][nt][2] + b0, v11 = acc[mt][nt][3] + b1;
            if (GELU) {
                v00 = 0.5f * v00 * (1.0f + erff(v00 * 0.70710678118654752f));
                v01 = 0.5f * v01 * (1.0f + erff(v01 * 0.70710678118654752f));
                v10 = 0.5f * v10 * (1.0f + erff(v10 * 0.70710678118654752f));
                v11 = 0.5f * v11 * (1.0f + erff(v11 * 0.70710678118654752f));
            }
            if (res) {
                v00 += res[(size_t)r0 * N + col];
                v01 += res[(size_t)r0 * N + col + 1];
                v10 += res[(size_t)(r0 + 8) * N + col];
                v11 += res[(size_t)(r0 + 8) * N + col + 1];
            }
            float2 o0 = {v00, v01}, o1 = {v10, v11};
            *(float2*)(C + (size_t)r0 * N + col) = o0;
            *(float2*)(C + (size_t)(r0 + 8) * N + col) = o1;
        }
    }
}

// ---------------- fused flash attention: Q in registers, 2 CTAs/SM ----------------
#define FLD 68
#define FSMEM_FLOATS (64 * FLD + 64 * FLD + 128 * FLD + 64)

template <int CAUSAL>
__global__ __launch_bounds__(256, 2) void flash_kernel(
    const float* __restrict__ Qp, const float* __restrict__ Kp,
    const float* __restrict__ Vp, const unsigned char* __restrict__ mask,
    float* __restrict__ Op, int Sk, int ldq, int ldk, int ldv,
    int qoff, int koff, int voff) {
    extern __shared__ float sm[];
    float* Ks = sm;                 // [64][FLD]
    float* Vs = Ks + 64 * FLD;      // [64][FLD]
    float* Ps = Vs + 64 * FLD;      // [128][FLD]
    float* Msk = Ps + 128 * FLD;    // [64]

    int tid = threadIdx.x, warp = tid >> 5, lane = tid & 31;
    int g = lane >> 2, tg = lane & 3;
    int bh = blockIdx.y, b = bh >> 4, h = bh & 15;
    int t0 = blockIdx.x * 128;
    int mrow = warp * 16 + g;

    // Q fragments in registers (loop-invariant per warp; scale + tf32 folded)
    float qf[8][4];
    {
        const float* q0 = Qp + (size_t)(b * TT + t0 + mrow) * ldq + qoff + h * HD;
        const float* q1 = q0 + (size_t)8 * ldq;
        #pragma unroll
        for (int kb = 0; kb < 8; kb++) {
            int k0 = kb * 8;
            qf[kb][0] = tf32r(q0[k0 + tg] * 0.125f);
            qf[kb][1] = tf32r(q1[k0 + tg] * 0.125f);
            qf[kb][2] = tf32r(q0[k0 + tg + 4] * 0.125f);
            qf[kb][3] = tf32r(q1[k0 + tg + 4] * 0.125f);
        }
    }

    float m0 = -1e30f, m1 = -1e30f, l0 = 0.f, l1 = 0.f;
    float o[8][4];
    #pragma unroll
    for (int i = 0; i < 8; i++)
        #pragma unroll
        for (int j = 0; j < 4; j++) o[i][j] = 0.f;

    int s_end = CAUSAL ? (t0 + 128 < Sk ? t0 + 128 : Sk) : Sk;
    for (int s0 = 0; s0 < s_end; s0 += 64) {
        __syncthreads();
        // stage K, V (tf32) and mask values
        {
            int row = tid >> 2;
            int c0 = (tid & 3) * 16;
            const float* ksrc = Kp + (size_t)(b * Sk + s0 + row) * ldk + koff + h * HD + c0;
            const float* vsrc = Vp + (size_t)(b * Sk + s0 + row) * ldv + voff + h * HD + c0;
            float* kd = Ks + row * FLD + c0;
            float* vd = Vs + row * FLD + c0;
            #pragma unroll
            for (int i = 0; i < 4; i++) {
                float4 kv = *(const float4*)(ksrc + i * 4);
                float4 vv = *(const float4*)(vsrc + i * 4);
                kd[i * 4 + 0] = tf32r(kv.x); kd[i * 4 + 1] = tf32r(kv.y);
                kd[i * 4 + 2] = tf32r(kv.z); kd[i * 4 + 3] = tf32r(kv.w);
                vd[i * 4 + 0] = tf32r(vv.x); vd[i * 4 + 1] = tf32r(vv.y);
                vd[i * 4 + 2] = tf32r(vv.z); vd[i * 4 + 3] = tf32r(vv.w);
            }
            if (tid < 64) Msk[tid] = mask[(size_t)b * Sk + s0 + tid] ? -1e30f : 0.f;
        }
        __syncthreads();

        // S = Q K^T (per warp: 16 x 64)
        float s_acc[8][4];
        #pragma unroll
        for (int nt = 0; nt < 8; nt++)
            #pragma unroll
            for (int j = 0; j < 4; j++) s_acc[nt][j] = 0.f;
        #pragma unroll
        for (int kb = 0; kb < 8; kb++) {
            int k0 = kb * 8;
            #pragma unroll
            for (int nt = 0; nt < 8; nt++) {
                float bf[2];
                bf[0] = Ks[(nt * 8 + g) * FLD + k0 + tg];
                bf[1] = Ks[(nt * 8 + g) * FLD + k0 + tg + 4];
                mma_tf32(s_acc[nt], qf[kb], bf);
            }
        }

        // masks
        int r0g = t0 + warp * 16 + g, r1g = r0g + 8;
        bool need_causal = CAUSAL && (s0 + 63 > t0 + warp * 16);
        #pragma unroll
        for (int nt = 0; nt < 8; nt++) {
            int cl = nt * 8 + 2 * tg;
            float mv0 = Msk[cl], mv1 = Msk[cl + 1];
            s_acc[nt][0] += mv0; s_acc[nt][1] += mv1;
            s_acc[nt][2] += mv0; s_acc[nt][3] += mv1;
            if (need_causal) {
                int cg = s0 + cl;
                if (cg > r0g) s_acc[nt][0] = -1e30f;
                if (cg + 1 > r0g) s_acc[nt][1] = -1e30f;
                if (cg > r1g) s_acc[nt][2] = -1e30f;
                if (cg + 1 > r1g) s_acc[nt][3] = -1e30f;
            }
        }

        // online softmax
        float mx0 = -1e30f, mx1 = -1e30f;
        #pragma unroll
        for (int nt = 0; nt < 8; nt++) {
            mx0 = fmaxf(mx0, fmaxf(s_acc[nt][0], s_acc[nt][1]));
            mx1 = fmaxf(mx1, fmaxf(s_acc[nt][2], s_acc[nt][3]));
        }
        mx0 = fmaxf(mx0, __shfl_xor_sync(0xffffffff, mx0, 1));
        mx0 = fmaxf(mx0, __shfl_xor_sync(0xffffffff, mx0, 2));
        mx1 = fmaxf(mx1, __shfl_xor_sync(0xffffffff, mx1, 1));
        mx1 = fmaxf(mx1, __shfl_xor_sync(0xffffffff, mx1, 2));
        float mn0 = fmaxf(m0, mx0), mn1 = fmaxf(m1, mx1);
        float a0 = __expf(m0 - mn0), a1 = __expf(m1 - mn1);
        m0 = mn0; m1 = mn1;

        float rs0 = 0.f, rs1 = 0.f;
        #pragma unroll
        for (int nt = 0; nt < 8; nt++) {
            float p0 = __expf(s_acc[nt][0] - mn0);
            float p1 = __expf(s_acc[nt][1] - mn0);
            float p2 = __expf(s_acc[nt][2] - mn1);
            float p3 = __expf(s_acc[nt][3] - mn1);
            rs0 += p0 + p1; rs1 += p2 + p3;
            int cl = nt * 8 + 2 * tg;
            Ps[mrow * FLD + cl] = tf32r(p0);
            Ps[mrow * FLD + cl + 1] = tf32r(p1);
            Ps[(mrow + 8) * FLD + cl] = tf32r(p2);
            Ps[(mrow + 8) * FLD + cl + 1] = tf32r(p3);
        }
        rs0 += __shfl_xor_sync(0xffffffff, rs0, 1);
        rs0 += __shfl_xor_sync(0xffffffff, rs0, 2);
        rs1 += __shfl_xor_sync(0xffffffff, rs1, 1);
        rs1 += __shfl_xor_sync(0xffffffff, rs1, 2);
        l0 = l0 * a0 + rs0;
        l1 = l1 * a1 + rs1;

        #pragma unroll
        for (int nt = 0; nt < 8; nt++) {
            o[nt][0] *= a0; o[nt][1] *= a0;
            o[nt][2] *= a1; o[nt][3] *= a1;
        }
        __syncwarp();

        // O += P @ V  (k-dim = 64 keys)
        #pragma unroll
        for (int kb = 0; kb < 8; kb++) {
            int k0 = kb * 8;
            float af[4];
            af[0] = Ps[mrow * FLD + k0 + tg];
            af[1] = Ps[(mrow + 8) * FLD + k0 + tg];
            af[2] = Ps[mrow * FLD + k0 + tg + 4];
            af[3] = Ps[(mrow + 8) * FLD + k0 + tg + 4];
            #pragma unroll
            for (int nt = 0; nt < 8; nt++) {
                float bf[2];
                bf[0] = Vs[(k0 + tg) * FLD + nt * 8 + g];
                bf[1] = Vs[(k0 + tg + 4) * FLD + nt * 8 + g];
                mma_tf32(o[nt], af, bf);
            }
        }
    }

    // epilogue: O / l  -> out[b, t, h*64 + d]
    float inv0 = 1.0f / l0, inv1 = 1.0f / l1;
    int row0 = t0 + warp * 16 + g;
    #pragma unroll
    for (int nt = 0; nt < 8; nt++) {
        int col = h * HD + nt * 8 + 2 * tg;
        float2 v0 = {o[nt][0] * inv0, o[nt][1] * inv0};
        float2 v1 = {o[nt][2] * inv1, o[nt][3] * inv1};
        *(float2*)(Op + (size_t)(b * TT + row0) * DDEC + col) = v0;
        *(float2*)(Op + (size_t)(b * TT + row0 + 8) * DDEC + col) = v1;
    }
}

// ---------------- launch ----------------
extern "C" void kernel_launch(void* const* d_in, const int* in_sizes, int n_in,
                              void* d_out, int out_size) {
    (void)in_sizes; (void)n_in; (void)out_size;
    const float* x      = (const float*)d_in[0];
    const float* enc    = (const float*)d_in[1];
    const unsigned char* tgt_mask = (const unsigned char*)d_in[2];
    const unsigned char* enc_mask = (const unsigned char*)d_in[3];
    const float* ln1_w  = (const float*)d_in[4];
    const float* ln1_b  = (const float*)d_in[5];
    const float* qkv_w  = (const float*)d_in[6];
    const float* qkv_b  = (const float*)d_in[7];
    const float* proj_w = (const float*)d_in[8];
    const float* proj_b = (const float*)d_in[9];
    const float* ln2_w  = (const float*)d_in[10];
    const float* ln2_b  = (const float*)d_in[11];
    const float* q_w    = (const float*)d_in[12];
    const float* q_b    = (const float*)d_in[13];
    const float* k_w    = (const float*)d_in[14];
    const float* k_b    = (const float*)d_in[15];
    const float* v_w    = (const float*)d_in[16];
    const float* v_b    = (const float*)d_in[17];
    const float* out_w  = (const float*)d_in[18];
    const float* out_b  = (const float*)d_in[19];
    const float* ln3_w  = (const float*)d_in[20];
    const float* ln3_b  = (const float*)d_in[21];
    const float* mlp1_w = (const float*)d_in[22];
    const float* mlp1_b = (const float*)d_in[23];
    const float* mlp2_w = (const float*)d_in[24];
    const float* mlp2_b = (const float*)d_in[25];
    float* out = (float*)d_out;

    float *h, *qkv, *tmp, *x1, *x2, *kc, *vc, *mlp;
    cudaGetSymbolAddress((void**)&h, g_h);
    cudaGetSymbolAddress((void**)&qkv, g_qkv);
    cudaGetSymbolAddress((void**)&tmp, g_tmp);
    cudaGetSymbolAddress((void**)&x1, g_x1);
    cudaGetSymbolAddress((void**)&x2, g_x2);
    cudaGetSymbolAddress((void**)&kc, g_kc);
    cudaGetSymbolAddress((void**)&vc, g_vc);
    cudaGetSymbolAddress((void**)&mlp, g_mlp);

    const int smem_bytes = SMEM_GEMM * 4;
    const int fsmem_bytes = FSMEM_FLOATS * 4;
    static int attr_set = 0;
    if (!attr_set) {
        cudaFuncSetAttribute(gemm_tf32_kernel<false>,
                             cudaFuncAttributeMaxDynamicSharedMemorySize, smem_bytes);
        cudaFuncSetAttribute(gemm_tf32_kernel<true>,
                             cudaFuncAttributeMaxDynamicSharedMemorySize, smem_bytes);
        cudaFuncSetAttribute(flash_kernel<0>,
                             cudaFuncAttributeMaxDynamicSharedMemorySize, fsmem_bytes);
        cudaFuncSetAttribute(flash_kernel<1>,
                             cudaFuncAttributeMaxDynamicSharedMemorySize, fsmem_bytes);
        attr_set = 1;
    }

    const int M = BB * TT;   // 4096
    const int Me = BB * SS;  // 2304

    // ---- self-attention ----
    ln_kernel<<<M, 256>>>(x, ln1_w, ln1_b, h);
    gemm_tf32_kernel<false><<<dim3(3 * DDEC / 128, M / 128), 256, smem_bytes>>>(h, qkv_w, qkv_b, nullptr, qkv, M, 3 * DDEC, DDEC);
    flash_kernel<1><<<dim3(TT / 128, BB * HH), 256, fsmem_bytes>>>(
        qkv, qkv, qkv, tgt_mask, tmp, TT, 3 * DDEC, 3 * DDEC, 3 * DDEC, 0, DDEC, 2 * DDEC);
    gemm_tf32_kernel<false><<<dim3(DDEC / 128, M / 128), 256, smem_bytes>>>(tmp, proj_w, proj_b, x, x1, M, DDEC, DDEC);

    // ---- cross-attention ----
    ln_kernel<<<M, 256>>>(x1, ln2_w, ln2_b, h);
    gemm_tf32_kernel<false><<<dim3(DDEC / 128, M / 128), 256, smem_bytes>>>(h, q_w, q_b, nullptr, qkv, M, DDEC, DDEC);
    gemm_tf32_kernel<false><<<dim3(DDEC / 128, Me / 128), 256, smem_bytes>>>(enc, k_w, k_b, nullptr, kc, Me, DDEC, 768);
    gemm_tf32_kernel<false><<<dim3(DDEC / 128, Me / 128), 256, smem_bytes>>>(enc, v_w, v_b, nullptr, vc, Me, DDEC, 768);
    flash_kernel<0><<<dim3(TT / 128, BB * HH), 256, fsmem_bytes>>>(
        qkv, kc, vc, enc_mask, tmp, SS, DDEC, DDEC, DDEC, 0, 0, 0);
    gemm_tf32_kernel<false><<<dim3(DDEC / 128, M / 128), 256, smem_bytes>>>(tmp, out_w, out_b, x1, x2, M, DDEC, DDEC);

    // ---- MLP ----
    ln_kernel<<<M, 256>>>(x2, ln3_w, ln3_b, h);
    gemm_tf32_kernel<true><<<dim3(DMLP / 128, M / 128), 256, smem_bytes>>>(h, mlp1_w, mlp1_b, nullptr, mlp, M, DMLP, DDEC);
    gemm_tf32_kernel<false><<<dim3(DDEC / 128, M / 128), 256, smem_bytes>>>(mlp, mlp2_w, mlp2_b, x2, out, M, DDEC, DMLP);
}

// round 9
// speedup vs baseline: 1.4037x; 1.2636x over previous
#include <cuda_runtime.h>
#include <math.h>
#include <stdint.h>

#define BB 4
#define TT 1024
#define SS 576
#define HH 16
#define HD 64
#define DDEC 1024
#define DMLP 4096

// ---------------- scratch (device globals; no allocation allowed) ----------------
__device__ float g_h[4194304];        // LN output (tf32-rounded)
__device__ float g_qkv[12582912];     // qkv / q
__device__ float g_tmp[4194304];      // flash out (tf32-rounded)
__device__ float g_x1[4194304];
__device__ float g_x2[4194304];
__device__ float g_kc[2359296];       // cross K
__device__ float g_vc[2359296];       // cross V
__device__ float g_mlp[16777216];     // mlp hidden (tf32-rounded)
__device__ float g_wr[18022400];      // rounded weights [K,N] + rounded enc

// ---------------- helpers ----------------
__device__ __forceinline__ float tf32r(float x) {
    uint32_t u;
    asm("cvt.rna.tf32.f32 %0, %1;" : "=r"(u) : "f"(x));
    return __uint_as_float(u);
}

__device__ __forceinline__ void mma_tf32(float (&d)[4], const float (&a)[4], const float (&b)[2]) {
    asm volatile(
        "mma.sync.aligned.m16n8k8.row.col.f32.tf32.tf32.f32 "
        "{%0,%1,%2,%3}, {%4,%5,%6,%7}, {%8,%9}, {%0,%1,%2,%3};"
        : "+f"(d[0]), "+f"(d[1]), "+f"(d[2]), "+f"(d[3])
        : "r"(__float_as_uint(a[0])), "r"(__float_as_uint(a[1])),
          "r"(__float_as_uint(a[2])), "r"(__float_as_uint(a[3])),
          "r"(__float_as_uint(b[0])), "r"(__float_as_uint(b[1])));
}

__device__ __forceinline__ void cp_async16(void* sdst, const void* gsrc) {
    uint32_t sa = (uint32_t)__cvta_generic_to_shared(sdst);
    asm volatile("cp.async.cg.shared.global [%0], [%1], 16;" :: "r"(sa), "l"(gsrc));
}
__device__ __forceinline__ void cp_commit() { asm volatile("cp.async.commit_group;"); }
template <int N>
__device__ __forceinline__ void cp_wait() { asm volatile("cp.async.wait_group %0;" :: "n"(N)); }

// ---------------- round fp32 -> tf32(RNA) ----------------
__global__ void round_kernel(const float* __restrict__ src, float* __restrict__ dst, int n4) {
    int i = blockIdx.x * 256 + threadIdx.x;
    if (i < n4) {
        float4 v = ((const float4*)src)[i];
        v.x = tf32r(v.x); v.y = tf32r(v.y); v.z = tf32r(v.z); v.w = tf32r(v.w);
        ((float4*)dst)[i] = v;
    }
}

// ---------------- LayerNorm (tf32-rounded output) ----------------
__global__ void ln_kernel(const float* __restrict__ x, const float* __restrict__ w,
                          const float* __restrict__ b, float* __restrict__ out) {
    __shared__ float red[256];
    int row = blockIdx.x, tid = threadIdx.x;
    const float4* xr = (const float4*)(x + (size_t)row * DDEC);
    float4 v = xr[tid];
    red[tid] = v.x + v.y + v.z + v.w;
    __syncthreads();
    #pragma unroll
    for (int o = 128; o > 0; o >>= 1) { if (tid < o) red[tid] += red[tid + o]; __syncthreads(); }
    float mean = red[0] * (1.0f / 1024.0f);
    __syncthreads();
    float dx = v.x - mean, dy = v.y - mean, dz = v.z - mean, dw = v.w - mean;
    red[tid] = dx * dx + dy * dy + dz * dz + dw * dw;
    __syncthreads();
    #pragma unroll
    for (int o = 128; o > 0; o >>= 1) { if (tid < o) red[tid] += red[tid + o]; __syncthreads(); }
    float rstd = rsqrtf(red[0] * (1.0f / 1024.0f) + 1e-5f);
    float4 wv = ((const float4*)w)[tid];
    float4 bv = ((const float4*)b)[tid];
    float4 o4;
    o4.x = tf32r(dx * rstd * wv.x + bv.x);
    o4.y = tf32r(dy * rstd * wv.y + bv.y);
    o4.z = tf32r(dz * rstd * wv.z + bv.z);
    o4.w = tf32r(dw * rstd * wv.w + bv.w);
    ((float4*)(out + (size_t)row * DDEC))[tid] = o4;
}

// ---------------- tf32 GEMM: 128x128x32 block, 4 warps (2x2) of 64x64, 2 CTAs/SM ----------------
#define AS_LD 36
#define BS_LD 132
#define G_STAGE (128 * AS_LD + 32 * BS_LD)   // 8832 floats
#define GSMEM_BYTES (3 * G_STAGE * 4)        // 105984

template <bool GELU>
__global__ __launch_bounds__(128, 2) void gemm_tf32_kernel(
    const float* __restrict__ A, const float* __restrict__ W,
    const float* __restrict__ bias, const float* __restrict__ res,
    float* __restrict__ C, int M, int N, int K) {
    extern __shared__ float smem[];

    int tid = threadIdx.x;
    int warp = tid >> 5, lane = tid & 31;
    int warp_m = warp >> 1, warp_n = warp & 1;
    int g = lane >> 2, tg = lane & 3;
    int bm = blockIdx.y * 128, bn = blockIdx.x * 128;
    const float* Ag = A + (size_t)bm * K;
    const float* Wg = W + bn;

    float acc[4][8][4];
    #pragma unroll
    for (int i = 0; i < 4; i++)
        #pragma unroll
        for (int j = 0; j < 8; j++)
            #pragma unroll
            for (int c = 0; c < 4; c++) acc[i][j][c] = 0.f;

    int kTiles = K >> 5;

    // producer: 128 threads, A: 1024 chunks (8/thread), B: 1024 chunks (8/thread)
    auto load_tile = [&](int kt) {
        float* As = smem + (kt % 3) * G_STAGE;
        float* Bs = As + 128 * AS_LD;
        int kof = kt * 32;
        #pragma unroll
        for (int i = 0; i < 8; i++) {
            int c = tid + i * 128;
            int row = c >> 3, c16 = c & 7;
            cp_async16(&As[row * AS_LD + c16 * 4], Ag + (size_t)row * K + kof + c16 * 4);
        }
        #pragma unroll
        for (int i = 0; i < 8; i++) {
            int c = tid + i * 128;
            int row = c >> 5, c16 = c & 31;
            cp_async16(&Bs[row * BS_LD + c16 * 4], Wg + (size_t)(kof + row) * N + c16 * 4);
        }
        cp_commit();
    };

    load_tile(0);
    load_tile(1);

    for (int kt = 0; kt < kTiles; kt++) {
        cp_wait<1>();
        __syncthreads();
        float* Ab = smem + (kt % 3) * G_STAGE;
        float* Bb = Ab + 128 * AS_LD;

        #pragma unroll
        for (int kk = 0; kk < 4; kk++) {
            int kb = kk << 3;
            float af[4][4], bf[8][2];
            #pragma unroll
            for (int mt = 0; mt < 4; mt++) {
                int m0 = warp_m * 64 + mt * 16 + g;
                af[mt][0] = Ab[m0 * AS_LD + kb + tg];
                af[mt][1] = Ab[(m0 + 8) * AS_LD + kb + tg];
                af[mt][2] = Ab[m0 * AS_LD + kb + tg + 4];
                af[mt][3] = Ab[(m0 + 8) * AS_LD + kb + tg + 4];
            }
            #pragma unroll
            for (int nt = 0; nt < 8; nt++) {
                int n0 = warp_n * 64 + nt * 8 + g;
                bf[nt][0] = Bb[(kb + tg) * BS_LD + n0];
                bf[nt][1] = Bb[(kb + tg + 4) * BS_LD + n0];
            }
            #pragma unroll
            for (int mt = 0; mt < 4; mt++)
                #pragma unroll
                for (int nt = 0; nt < 8; nt++) mma_tf32(acc[mt][nt], af[mt], bf[nt]);
        }

        if (kt + 2 < kTiles) load_tile(kt + 2);
    }

    #pragma unroll
    for (int mt = 0; mt < 4; mt++) {
        int r0 = bm + warp_m * 64 + mt * 16 + g;
        #pragma unroll
        for (int nt = 0; nt < 8; nt++) {
            int col = bn + warp_n * 64 + nt * 8 + tg * 2;
            float b0 = bias[col], b1 = bias[col + 1];
            float v00 = acc[mt][nt][0] + b0, v01 = acc[mt][nt][1] + b1;
            float v10 = acc[mt][nt][2] + b0, v11 = acc[mt][nt][3] + b1;
            if (GELU) {
                v00 = tf32r(0.5f * v00 * (1.0f + erff(v00 * 0.70710678118654752f)));
                v01 = tf32r(0.5f * v01 * (1.0f + erff(v01 * 0.70710678118654752f)));
                v10 = tf32r(0.5f * v10 * (1.0f + erff(v10 * 0.70710678118654752f)));
                v11 = tf32r(0.5f * v11 * (1.0f + erff(v11 * 0.70710678118654752f)));
            }
            if (res) {
                v00 += res[(size_t)r0 * N + col];
                v01 += res[(size_t)r0 * N + col + 1];
                v10 += res[(size_t)(r0 + 8) * N + col];
                v11 += res[(size_t)(r0 + 8) * N + col + 1];
            }
            float2 o0 = {v00, v01}, o1 = {v10, v11};
            *(float2*)(C + (size_t)r0 * N + col) = o0;
            *(float2*)(C + (size_t)(r0 + 8) * N + col) = o1;
        }
    }
}

// ---------------- fused flash attention (tf32 SIMT core; Q in regs; heavy-first) ----------------
#define FLD 68
#define FSMEM_FLOATS (64 * FLD + 64 * FLD + 128 * FLD + 64)

template <int CAUSAL>
__global__ __launch_bounds__(256, 2) void flash_kernel(
    const float* __restrict__ Qp, const float* __restrict__ Kp,
    const float* __restrict__ Vp, const unsigned char* __restrict__ mask,
    float* __restrict__ Op, int Sk, int ldq, int ldk, int ldv,
    int qoff, int koff, int voff) {
    extern __shared__ float sm[];
    float* Ks = sm;
    float* Vs = Ks + 64 * FLD;
    float* Ps = Vs + 64 * FLD;
    float* Msk = Ps + 128 * FLD;

    int tid = threadIdx.x, warp = tid >> 5, lane = tid & 31;
    int g = lane >> 2, tg = lane & 3;
    int bh = blockIdx.y, b = bh >> 4, h = bh & 15;
    // heavy tiles (large t0) first for causal to reduce wave-tail imbalance
    int tb = CAUSAL ? (gridDim.x - 1 - blockIdx.x) : blockIdx.x;
    int t0 = tb * 128;
    int mrow = warp * 16 + g;

    float qf[8][4];
    {
        const float* q0 = Qp + (size_t)(b * TT + t0 + mrow) * ldq + qoff + h * HD;
        const float* q1 = q0 + (size_t)8 * ldq;
        #pragma unroll
        for (int kb = 0; kb < 8; kb++) {
            int k0 = kb * 8;
            qf[kb][0] = tf32r(q0[k0 + tg] * 0.125f);
            qf[kb][1] = tf32r(q1[k0 + tg] * 0.125f);
            qf[kb][2] = tf32r(q0[k0 + tg + 4] * 0.125f);
            qf[kb][3] = tf32r(q1[k0 + tg + 4] * 0.125f);
        }
    }

    float m0 = -1e30f, m1 = -1e30f, l0 = 0.f, l1 = 0.f;
    float o[8][4];
    #pragma unroll
    for (int i = 0; i < 8; i++)
        #pragma unroll
        for (int j = 0; j < 4; j++) o[i][j] = 0.f;

    int s_end = CAUSAL ? (t0 + 128 < Sk ? t0 + 128 : Sk) : Sk;
    for (int s0 = 0; s0 < s_end; s0 += 64) {
        __syncthreads();
        {
            int row = tid >> 2;
            int c0 = (tid & 3) * 16;
            const float* ksrc = Kp + (size_t)(b * Sk + s0 + row) * ldk + koff + h * HD + c0;
            const float* vsrc = Vp + (size_t)(b * Sk + s0 + row) * ldv + voff + h * HD + c0;
            float* kd = Ks + row * FLD + c0;
            float* vd = Vs + row * FLD + c0;
            #pragma unroll
            for (int i = 0; i < 4; i++) {
                float4 kv = *(const float4*)(ksrc + i * 4);
                float4 vv = *(const float4*)(vsrc + i * 4);
                kd[i * 4 + 0] = tf32r(kv.x); kd[i * 4 + 1] = tf32r(kv.y);
                kd[i * 4 + 2] = tf32r(kv.z); kd[i * 4 + 3] = tf32r(kv.w);
                vd[i * 4 + 0] = tf32r(vv.x); vd[i * 4 + 1] = tf32r(vv.y);
                vd[i * 4 + 2] = tf32r(vv.z); vd[i * 4 + 3] = tf32r(vv.w);
            }
            if (tid < 64) Msk[tid] = mask[(size_t)b * Sk + s0 + tid] ? -1e30f : 0.f;
        }
        __syncthreads();

        float s_acc[8][4];
        #pragma unroll
        for (int nt = 0; nt < 8; nt++)
            #pragma unroll
            for (int j = 0; j < 4; j++) s_acc[nt][j] = 0.f;
        #pragma unroll
        for (int kb = 0; kb < 8; kb++) {
            int k0 = kb * 8;
            #pragma unroll
            for (int nt = 0; nt < 8; nt++) {
                float bf[2];
                bf[0] = Ks[(nt * 8 + g) * FLD + k0 + tg];
                bf[1] = Ks[(nt * 8 + g) * FLD + k0 + tg + 4];
                mma_tf32(s_acc[nt], qf[kb], bf);
            }
        }

        int r0g = t0 + warp * 16 + g, r1g = r0g + 8;
        bool need_causal = CAUSAL && (s0 + 63 > t0 + warp * 16);
        #pragma unroll
        for (int nt = 0; nt < 8; nt++) {
            int cl = nt * 8 + 2 * tg;
            float mv0 = Msk[cl], mv1 = Msk[cl + 1];
            s_acc[nt][0] += mv0; s_acc[nt][1] += mv1;
            s_acc[nt][2] += mv0; s_acc[nt][3] += mv1;
            if (need_causal) {
                int cg = s0 + cl;
                if (cg > r0g) s_acc[nt][0] = -1e30f;
                if (cg + 1 > r0g) s_acc[nt][1] = -1e30f;
                if (cg > r1g) s_acc[nt][2] = -1e30f;
                if (cg + 1 > r1g) s_acc[nt][3] = -1e30f;
            }
        }

        float mx0 = -1e30f, mx1 = -1e30f;
        #pragma unroll
        for (int nt = 0; nt < 8; nt++) {
            mx0 = fmaxf(mx0, fmaxf(s_acc[nt][0], s_acc[nt][1]));
            mx1 = fmaxf(mx1, fmaxf(s_acc[nt][2], s_acc[nt][3]));
        }
        mx0 = fmaxf(mx0, __shfl_xor_sync(0xffffffff, mx0, 1));
        mx0 = fmaxf(mx0, __shfl_xor_sync(0xffffffff, mx0, 2));
        mx1 = fmaxf(mx1, __shfl_xor_sync(0xffffffff, mx1, 1));
        mx1 = fmaxf(mx1, __shfl_xor_sync(0xffffffff, mx1, 2));
        float mn0 = fmaxf(m0, mx0), mn1 = fmaxf(m1, mx1);
        float a0 = __expf(m0 - mn0), a1 = __expf(m1 - mn1);
        m0 = mn0; m1 = mn1;

        float rs0 = 0.f, rs1 = 0.f;
        #pragma unroll
        for (int nt = 0; nt < 8; nt++) {
            float p0 = __expf(s_acc[nt][0] - mn0);
            float p1 = __expf(s_acc[nt][1] - mn0);
            float p2 = __expf(s_acc[nt][2] - mn1);
            float p3 = __expf(s_acc[nt][3] - mn1);
            rs0 += p0 + p1; rs1 += p2 + p3;
            int cl = nt * 8 + 2 * tg;
            Ps[mrow * FLD + cl] = tf32r(p0);
            Ps[mrow * FLD + cl + 1] = tf32r(p1);
            Ps[(mrow + 8) * FLD + cl] = tf32r(p2);
            Ps[(mrow + 8) * FLD + cl + 1] = tf32r(p3);
        }
        rs0 += __shfl_xor_sync(0xffffffff, rs0, 1);
        rs0 += __shfl_xor_sync(0xffffffff, rs0, 2);
        rs1 += __shfl_xor_sync(0xffffffff, rs1, 1);
        rs1 += __shfl_xor_sync(0xffffffff, rs1, 2);
        l0 = l0 * a0 + rs0;
        l1 = l1 * a1 + rs1;

        #pragma unroll
        for (int nt = 0; nt < 8; nt++) {
            o[nt][0] *= a0; o[nt][1] *= a0;
            o[nt][2] *= a1; o[nt][3] *= a1;
        }
        __syncwarp();

        #pragma unroll
        for (int kb = 0; kb < 8; kb++) {
            int k0 = kb * 8;
            float af[4];
            af[0] = Ps[mrow * FLD + k0 + tg];
            af[1] = Ps[(mrow + 8) * FLD + k0 + tg];
            af[2] = Ps[mrow * FLD + k0 + tg + 4];
            af[3] = Ps[(mrow + 8) * FLD + k0 + tg + 4];
            #pragma unroll
            for (int nt = 0; nt < 8; nt++) {
                float bf[2];
                bf[0] = Vs[(k0 + tg) * FLD + nt * 8 + g];
                bf[1] = Vs[(k0 + tg + 4) * FLD + nt * 8 + g];
                mma_tf32(o[nt], af, bf);
            }
        }
    }

    // epilogue: O / l, tf32-rounded (feeds proj/out GEMM as A operand)
    float inv0 = 1.0f / l0, inv1 = 1.0f / l1;
    int row0 = t0 + warp * 16 + g;
    #pragma unroll
    for (int nt = 0; nt < 8; nt++) {
        int col = h * HD + nt * 8 + 2 * tg;
        float2 v0 = {tf32r(o[nt][0] * inv0), tf32r(o[nt][1] * inv0)};
        float2 v1 = {tf32r(o[nt][2] * inv1), tf32r(o[nt][3] * inv1)};
        *(float2*)(Op + (size_t)(b * TT + row0) * DDEC + col) = v0;
        *(float2*)(Op + (size_t)(b * TT + row0 + 8) * DDEC + col) = v1;
    }
}

// ---------------- launch ----------------
extern "C" void kernel_launch(void* const* d_in, const int* in_sizes, int n_in,
                              void* d_out, int out_size) {
    (void)in_sizes; (void)n_in; (void)out_size;
    const float* x      = (const float*)d_in[0];
    const float* enc    = (const float*)d_in[1];
    const unsigned char* tgt_mask = (const unsigned char*)d_in[2];
    const unsigned char* enc_mask = (const unsigned char*)d_in[3];
    const float* ln1_w  = (const float*)d_in[4];
    const float* ln1_b  = (const float*)d_in[5];
    const float* qkv_w  = (const float*)d_in[6];
    const float* qkv_b  = (const float*)d_in[7];
    const float* proj_w = (const float*)d_in[8];
    const float* proj_b = (const float*)d_in[9];
    const float* ln2_w  = (const float*)d_in[10];
    const float* ln2_b  = (const float*)d_in[11];
    const float* q_w    = (const float*)d_in[12];
    const float* q_b    = (const float*)d_in[13];
    const float* k_w    = (const float*)d_in[14];
    const float* k_b    = (const float*)d_in[15];
    const float* v_w    = (const float*)d_in[16];
    const float* v_b    = (const float*)d_in[17];
    const float* out_w  = (const float*)d_in[18];
    const float* out_b  = (const float*)d_in[19];
    const float* ln3_w  = (const float*)d_in[20];
    const float* ln3_b  = (const float*)d_in[21];
    const float* mlp1_w = (const float*)d_in[22];
    const float* mlp1_b = (const float*)d_in[23];
    const float* mlp2_w = (const float*)d_in[24];
    const float* mlp2_b = (const float*)d_in[25];
    float* out = (float*)d_out;

    float *h, *qkv, *tmp, *x1, *x2, *kc, *vc, *mlp, *wr;
    cudaGetSymbolAddress((void**)&h, g_h);
    cudaGetSymbolAddress((void**)&qkv, g_qkv);
    cudaGetSymbolAddress((void**)&tmp, g_tmp);
    cudaGetSymbolAddress((void**)&x1, g_x1);
    cudaGetSymbolAddress((void**)&x2, g_x2);
    cudaGetSymbolAddress((void**)&kc, g_kc);
    cudaGetSymbolAddress((void**)&vc, g_vc);
    cudaGetSymbolAddress((void**)&mlp, g_mlp);
    cudaGetSymbolAddress((void**)&wr, g_wr);

    float* r_qkv  = wr;
    float* r_proj = wr + 3145728;
    float* r_q    = wr + 4194304;
    float* r_k    = wr + 5242880;
    float* r_v    = wr + 6029312;
    float* r_out  = wr + 6815744;
    float* r_mlp1 = wr + 7864320;
    float* r_mlp2 = wr + 12058624;
    float* r_enc  = wr + 16252928;

    const int fsmem_bytes = FSMEM_FLOATS * 4;
    static int attr_set = 0;
    if (!attr_set) {
        cudaFuncSetAttribute(gemm_tf32_kernel<false>,
                             cudaFuncAttributeMaxDynamicSharedMemorySize, GSMEM_BYTES);
        cudaFuncSetAttribute(gemm_tf32_kernel<true>,
                             cudaFuncAttributeMaxDynamicSharedMemorySize, GSMEM_BYTES);
        cudaFuncSetAttribute(flash_kernel<0>,
                             cudaFuncAttributeMaxDynamicSharedMemorySize, fsmem_bytes);
        cudaFuncSetAttribute(flash_kernel<1>,
                             cudaFuncAttributeMaxDynamicSharedMemorySize, fsmem_bytes);
        attr_set = 1;
    }

    const int M = BB * TT;   // 4096
    const int Me = BB * SS;  // 2304

    // ---- round weights + enc to tf32 (B / enc operands) ----
    auto rr = [](const float* s, float* d, int n) {
        round_kernel<<<(n / 4 + 255) / 256, 256>>>(s, d, n / 4);
    };
    rr(qkv_w, r_qkv, 3145728);
    rr(proj_w, r_proj, 1048576);
    rr(q_w, r_q, 1048576);
    rr(k_w, r_k, 786432);
    rr(v_w, r_v, 786432);
    rr(out_w, r_out, 1048576);
    rr(mlp1_w, r_mlp1, 4194304);
    rr(mlp2_w, r_mlp2, 4194304);
    rr(enc, r_enc, 1769472);

    // ---- self-attention ----
    ln_kernel<<<M, 256>>>(x, ln1_w, ln1_b, h);
    gemm_tf32_kernel<false><<<dim3(24, 32), 128, GSMEM_BYTES>>>(h, r_qkv, qkv_b, nullptr, qkv, M, 3 * DDEC, DDEC);
    flash_kernel<1><<<dim3(TT / 128, BB * HH), 256, fsmem_bytes>>>(
        qkv, qkv, qkv, tgt_mask, tmp, TT, 3 * DDEC, 3 * DDEC, 3 * DDEC, 0, DDEC, 2 * DDEC);
    gemm_tf32_kernel<false><<<dim3(8, 32), 128, GSMEM_BYTES>>>(tmp, r_proj, proj_b, x, x1, M, DDEC, DDEC);

    // ---- cross-attention ----
    ln_kernel<<<M, 256>>>(x1, ln2_w, ln2_b, h);
    gemm_tf32_kernel<false><<<dim3(8, 32), 128, GSMEM_BYTES>>>(h, r_q, q_b, nullptr, qkv, M, DDEC, DDEC);
    gemm_tf32_kernel<false><<<dim3(8, 18), 128, GSMEM_BYTES>>>(r_enc, r_k, k_b, nullptr, kc, Me, DDEC, 768);
    gemm_tf32_kernel<false><<<dim3(8, 18), 128, GSMEM_BYTES>>>(r_enc, r_v, v_b, nullptr, vc, Me, DDEC, 768);
    flash_kernel<0><<<dim3(TT / 128, BB * HH), 256, fsmem_bytes>>>(
        qkv, kc, vc, enc_mask, tmp, SS, DDEC, DDEC, DDEC, 0, 0, 0);
    gemm_tf32_kernel<false><<<dim3(8, 32), 128, GSMEM_BYTES>>>(tmp, r_out, out_b, x1, x2, M, DDEC, DDEC);

    // ---- MLP ----
    ln_kernel<<<M, 256>>>(x2, ln3_w, ln3_b, h);
    gemm_tf32_kernel<true><<<dim3(32, 32), 128, GSMEM_BYTES>>>(h, r_mlp1, mlp1_b, nullptr, mlp, M, DMLP, DDEC);
    gemm_tf32_kernel<false><<<dim3(8, 32), 128, GSMEM_BYTES>>>(mlp, r_mlp2, mlp2_b, x2, out, M, DDEC, DMLP);
}